// round 15
// baseline (speedup 1.0000x reference)
#include <cuda_runtime.h>

#define NQ   6
#define DIM  64
#define TT   512
#define BB   128

// Fixed per-direction unitaries: U[dir][row][col], built by setup_kernel.
__device__ float2 U_g[2][DIM][DIM];

__device__ __forceinline__ float2 cmul(float2 a, float2 b) {
    return make_float2(a.x * b.x - a.y * b.y, a.x * b.y + a.y * b.x);
}
__device__ __forceinline__ float2 cadd(float2 a, float2 b) {
    return make_float2(a.x + b.x, a.y + b.y);
}

// ---------------------------------------------------------------------------
// Setup: build U = V(params) * Q(poly) as a 64x64 complex matrix per direction.
// ---------------------------------------------------------------------------
__global__ void setup_kernel(const float* __restrict__ poly,
                             const float* __restrict__ fwd_params,
                             const float* __restrict__ bwd_params)
{
    __shared__ float2 M[DIM][DIM];
    const int dir = blockIdx.x;
    const float* params = dir ? bwd_params : fwd_params;
    const int tid = threadIdx.x;  // 0..63

    for (int j = 0; j < DIM; ++j)
        M[tid][j] = make_float2(tid == j ? 1.f : 0.f, 0.f);
    __syncthreads();

    // QSVT block: 4 x (diagonal phase, then CNOT ring)
    for (int d = 0; d <= 3; ++d) {
        float theta = poly[d] * 3.14159265358979323846f;
        float sign  = (float)NQ - 2.0f * (float)__popc(tid);
        float ang   = -0.5f * theta * sign;
        float2 ph;
        sincosf(ang, &ph.y, &ph.x);
        for (int j = 0; j < DIM; ++j)
            M[tid][j] = cmul(ph, M[tid][j]);
        __syncthreads();
        for (int cw = 0; cw < NQ; ++cw) {
            int c  = (cw < NQ - 1) ? cw : NQ - 1;
            int t  = (cw < NQ - 1) ? cw + 1 : 0;
            int mc = 1 << (NQ - 1 - c), mt = 1 << (NQ - 1 - t);
            for (int i = 0; i < DIM; ++i) {
                if ((i & mc) && !(i & mt)) {
                    float2 a = M[i][tid];
                    M[i][tid]      = M[i | mt][tid];
                    M[i | mt][tid] = a;
                }
            }
            __syncthreads();
        }
    }

    // Variational layers
    int idx = 0;
    for (int layer = 0; layer < 2; ++layer) {
        for (int w = 0; w < NQ; ++w) {
            float al = params[idx], be = params[idx + 1], ga = params[idx + 2];
            idx += 3;
            float ca, sa, cb, sb, cg, sg;
            sincosf(0.5f * al, &sa, &ca);
            sincosf(0.5f * be, &sb, &cb);
            sincosf(0.5f * ga, &sg, &cg);
            float2 X00 = make_float2(ca, 0.f),  X01 = make_float2(0.f, -sa);
            float2 X10 = make_float2(0.f, -sa), X11 = make_float2(ca, 0.f);
            float2 Y00 = make_float2(cb, 0.f),  Y01 = make_float2(-sb, 0.f);
            float2 Y10 = make_float2(sb, 0.f),  Y11 = make_float2(cb, 0.f);
            float2 A00 = cadd(cmul(Y00, X00), cmul(Y01, X10));
            float2 A01 = cadd(cmul(Y00, X01), cmul(Y01, X11));
            float2 A10 = cadd(cmul(Y10, X00), cmul(Y11, X10));
            float2 A11 = cadd(cmul(Y10, X01), cmul(Y11, X11));
            float2 Z0 = make_float2(cg, -sg), Z1 = make_float2(cg, sg);
            float2 u00 = cmul(Z0, A00), u01 = cmul(Z0, A01);
            float2 u10 = cmul(Z1, A10), u11 = cmul(Z1, A11);
            int m = 1 << (NQ - 1 - w);
            for (int i0 = 0; i0 < DIM; ++i0) {
                if (i0 & m) continue;
                float2 a = M[i0][tid], b = M[i0 | m][tid];
                M[i0][tid]     = cadd(cmul(u00, a), cmul(u01, b));
                M[i0 | m][tid] = cadd(cmul(u10, a), cmul(u11, b));
            }
            __syncthreads();
        }
        for (int c = 0; c < NQ - 1; ++c) {
            int t  = c + 1;
            int mc = 1 << (NQ - 1 - c), mt = 1 << (NQ - 1 - t);
            for (int i = 0; i < DIM; ++i) {
                if ((i & mc) && !(i & mt)) {
                    float2 a = M[i][tid];
                    M[i][tid]      = M[i | mt][tid];
                    M[i | mt][tid] = a;
                }
            }
            __syncthreads();
        }
    }

    for (int j = 0; j < DIM; ++j)
        U_g[dir][tid][j] = M[tid][j];
}

// ---------------------------------------------------------------------------
// Main scan: 128 threads per lane. Thread tid = (row r = tid>>1, part = tid&1)
// where part selects re/im. Each thread accumulates ONE scalar through the
// matvec and all butterflies (RY coefficients are real -> re/im identical).
// Wire w <-> row bit (5-w) <-> tid bit (6-w). Wires 0,1 cross-warp (one fused
// 4-point shared exchange); wires 2..5 in-warp (two fused 4-point shfl
// levels). Same fusion for the probability WHT.
// ---------------------------------------------------------------------------
__global__ void __launch_bounds__(128)
hydra_kernel(const float* __restrict__ angles,
             const float* __restrict__ fwd_coeff,
             const float* __restrict__ bwd_coeff,
             float* __restrict__ out)
{
    const int cta  = blockIdx.x;
    const int dir  = cta >> 7;
    const int b    = cta & 127;
    const int tid  = threadIdx.x;
    const int r    = tid >> 1;     // row 0..63
    const int part = tid & 1;      // 0 = re, 1 = im

    // U row component in registers: Ureg[j] = (part ? Im : Re) U[r][j]
    float Ureg[DIM];
    {
        const float* Up = (const float*)U_g[dir][r];
#pragma unroll
        for (int j = 0; j < DIM; ++j)
            Ureg[j] = Up[2 * j + part];
    }

    __shared__ float2 xt[TT * NQ];   // (cos x/2, sin x/2) per (t, w)
    __shared__ float2 hcs[NQ];       // (cos h/2, sin h/2)
    __shared__ float4 p0v[DIM / 4];  // psi0 (real)
    __shared__ float  ex[128];       // RY cross-warp exchange
    __shared__ float  px[128];       // WHT cross-warp exchange

    // one-time: HALF-ANGLE cos/sin table for all steps (RY(x) coefficients)
    for (int idx = tid; idx < TT * NQ; idx += 128) {
        float a = angles[(size_t)b * (TT * NQ) + idx];
        float s, c; __sincosf(0.5f * a, &s, &c);
        xt[idx] = make_float2(c, s);
    }
    if (tid < NQ) hcs[tid] = make_float2(1.f, 0.f);   // h = 0

    float cf    = dir ? bwd_coeff[0] : fwd_coeff[0];
    float coeff = 1.0f / (1.0f + expf(-cf));
    const size_t outbase = (size_t)b * TT * NQ;

    const unsigned FULL = 0xFFFFFFFFu;
    // designated: part==0 and r a power of two -> holds z_{5-log2(r)}
    const bool desig = (part == 0) && (r != 0) && ((r & (r - 1)) == 0);
    const int  wire  = desig ? (5 - (31 - __clz(r))) : 0;

    float* p0s = (float*)p0v;

    __syncthreads();

    for (int step = 0; step < TT; ++step) {
        const int t = dir ? (TT - 1 - step) : step;

        // psi0[i] = prod_w (bit_{5-w}(i) ? sin : cos)(h_w/2)
        if (tid < DIM) {
            float v0 = 1.f;
#pragma unroll
            for (int w = 0; w < NQ; ++w) {
                float2 cs = hcs[w];
                v0 *= ((tid >> (NQ - 1 - w)) & 1) ? cs.y : cs.x;
            }
            p0s[tid] = v0;
        }
        __syncthreads();                               // (1) p0 ready

        // angle coefficients for this step (broadcast LDS, hidden under matvec)
        float2 X0 = xt[t * NQ + 0], X1 = xt[t * NQ + 1];
        float2 X2 = xt[t * NQ + 2], X3 = xt[t * NQ + 3];
        float2 X4 = xt[t * NQ + 4], X5 = xt[t * NQ + 5];

        // matvec: v = (row r of U, part) . p0
        float a0 = 0.f, a1 = 0.f, a2 = 0.f, a3 = 0.f;
#pragma unroll
        for (int jj = 0; jj < DIM / 4; ++jj) {
            float4 pv = p0v[jj];
            a0 = fmaf(Ureg[4 * jj + 0], pv.x, a0);
            a1 = fmaf(Ureg[4 * jj + 1], pv.y, a1);
            a2 = fmaf(Ureg[4 * jj + 2], pv.z, a2);
            a3 = fmaf(Ureg[4 * jj + 3], pv.w, a3);
        }
        float v = (a0 + a1) + (a2 + a3);

        // RY wires 0,1 (tid bits 6,5): fused 4-point via shared
        ex[tid] = v;
        __syncthreads();                               // (2)
        {
            float t5 = (tid & 64) ? X0.y : -X0.y;      // wire 0
            float t4 = (tid & 32) ? X1.y : -X1.y;      // wire 1
            float e64 = ex[tid ^ 64], e32 = ex[tid ^ 32], e96 = ex[tid ^ 96];
            v = X0.x * X1.x * v + (t5 * X1.x) * e64 + (X0.x * t4) * e32 + (t5 * t4) * e96;
        }
        // RY wires 2,3 (lane masks 16,8): fused
        {
            float u2 = (tid & 16) ? X2.y : -X2.y;
            float u3 = (tid &  8) ? X3.y : -X3.y;
            float b16 = __shfl_xor_sync(FULL, v, 16);
            float b8  = __shfl_xor_sync(FULL, v, 8);
            float b24 = __shfl_xor_sync(FULL, v, 24);
            v = X2.x * X3.x * v + (u2 * X3.x) * b16 + (X2.x * u3) * b8 + (u2 * u3) * b24;
        }
        // RY wires 4,5 (lane masks 4,2): fused
        {
            float u4 = (tid & 4) ? X4.y : -X4.y;
            float u5 = (tid & 2) ? X5.y : -X5.y;
            float b4 = __shfl_xor_sync(FULL, v, 4);
            float b2 = __shfl_xor_sync(FULL, v, 2);
            float b6 = __shfl_xor_sync(FULL, v, 6);
            v = X4.x * X5.x * v + (u4 * X5.x) * b4 + (X4.x * u5) * b2 + (u4 * u5) * b6;
        }

        // probability: p_r = re^2 + im^2 (pair across lane bit 0)
        float sq = v * v;
        float p  = sq + __shfl_xor_sync(FULL, sq, 1);

        // WHT in-warp (row bits 0..3 = lane masks 2,4,8,16), fused pairs
        {
            float g2 = (tid & 2) ? -1.f : 1.f;
            float g4 = (tid & 4) ? -1.f : 1.f;
            float c2 = __shfl_xor_sync(FULL, p, 2);
            float c4 = __shfl_xor_sync(FULL, p, 4);
            float c6 = __shfl_xor_sync(FULL, p, 6);
            p = g2 * g4 * p + g4 * c2 + g2 * c4 + c6;
        }
        {
            float g8  = (tid &  8) ? -1.f : 1.f;
            float g16 = (tid & 16) ? -1.f : 1.f;
            float c8  = __shfl_xor_sync(FULL, p, 8);
            float c16 = __shfl_xor_sync(FULL, p, 16);
            float c24 = __shfl_xor_sync(FULL, p, 24);
            p = g8 * g16 * p + g16 * c8 + g8 * c16 + c24;
        }
        // WHT cross-warp (row bits 4,5 = tid bits 5,6), fused 4-point
        px[tid] = p;
        __syncthreads();                               // (3)
        {
            float s4 = (tid & 32) ? -1.f : 1.f;
            float s5 = (tid & 64) ? -1.f : 1.f;
            float d32 = px[tid ^ 32], d64 = px[tid ^ 64], d96 = px[tid ^ 96];
            p = s4 * s5 * p + s5 * d32 + s4 * d64 + d96;
        }

        // designated threads (r = 1,2,4,8,16,32; part=0) hold z_w
        if (desig) {
            atomicAdd(&out[outbase + (size_t)t * NQ + wire], coeff * p);
            float sh, ch; __sincosf(0.5f * p, &sh, &ch);
            hcs[wire] = make_float2(ch, sh);
        }
        __syncthreads();                               // (4) hcs ready
    }
}

__global__ void zero_kernel(float* __restrict__ out, int n)
{
    int i = blockIdx.x * blockDim.x + threadIdx.x;
    if (i < n) out[i] = 0.f;
}

extern "C" void kernel_launch(void* const* d_in, const int* in_sizes, int n_in,
                              void* d_out, int out_size)
{
    const float* angles = (const float*)d_in[0];
    const float* poly   = (const float*)d_in[1];
    const float* fwdp   = (const float*)d_in[2];
    const float* bwdp   = (const float*)d_in[3];
    const float* fwdc   = (const float*)d_in[4];
    const float* bwdc   = (const float*)d_in[5];
    float* out = (float*)d_out;

    zero_kernel<<<(out_size + 255) / 256, 256>>>(out, out_size);
    setup_kernel<<<2, 64>>>(poly, fwdp, bwdp);
    hydra_kernel<<<2 * BB, 128>>>(angles, fwdc, bwdc, out);
}

// round 16
// speedup vs baseline: 1.7688x; 1.7688x over previous
#include <cuda_runtime.h>

#define NQ   6
#define DIM  64
#define TT   512
#define BB   128

typedef unsigned long long u64;

// Fixed per-direction unitaries: U[dir][row][col], built by setup_kernel.
__device__ float2 U_g[2][DIM][DIM];

__device__ __forceinline__ float2 cmul(float2 a, float2 b) {
    return make_float2(a.x * b.x - a.y * b.y, a.x * b.y + a.y * b.x);
}
__device__ __forceinline__ float2 cadd(float2 a, float2 b) {
    return make_float2(a.x + b.x, a.y + b.y);
}

// packed f32x2 helpers (sm_100+)
__device__ __forceinline__ void ffma2(u64& acc, u64 a, u64 b) {
    asm("fma.rn.f32x2 %0, %1, %2, %0;" : "+l"(acc) : "l"(a), "l"(b));
}
__device__ __forceinline__ u64 addf2(u64 a, u64 b) {
    u64 r; asm("add.rn.f32x2 %0, %1, %2;" : "=l"(r) : "l"(a), "l"(b)); return r;
}
__device__ __forceinline__ u64 pack2(float lo, float hi) {
    u64 r;
    asm("mov.b64 %0, {%1, %2};" : "=l"(r)
        : "r"(__float_as_uint(lo)), "r"(__float_as_uint(hi)));
    return r;
}
__device__ __forceinline__ void unpack2(u64 v, float& lo, float& hi) {
    unsigned a, b;
    asm("mov.b64 {%0, %1}, %2;" : "=r"(a), "=r"(b) : "l"(v));
    lo = __uint_as_float(a); hi = __uint_as_float(b);
}

// ---------------------------------------------------------------------------
// Setup: build U = V(params) * Q(poly) as a 64x64 complex matrix per direction.
// ---------------------------------------------------------------------------
__global__ void setup_kernel(const float* __restrict__ poly,
                             const float* __restrict__ fwd_params,
                             const float* __restrict__ bwd_params)
{
    __shared__ float2 M[DIM][DIM];
    const int dir = blockIdx.x;
    const float* params = dir ? bwd_params : fwd_params;
    const int tid = threadIdx.x;  // 0..63

    for (int j = 0; j < DIM; ++j)
        M[tid][j] = make_float2(tid == j ? 1.f : 0.f, 0.f);
    __syncthreads();

    // QSVT block: 4 x (diagonal phase, then CNOT ring)
    for (int d = 0; d <= 3; ++d) {
        float theta = poly[d] * 3.14159265358979323846f;
        float sign  = (float)NQ - 2.0f * (float)__popc(tid);
        float ang   = -0.5f * theta * sign;
        float2 ph;
        sincosf(ang, &ph.y, &ph.x);
        for (int j = 0; j < DIM; ++j)
            M[tid][j] = cmul(ph, M[tid][j]);
        __syncthreads();
        for (int cw = 0; cw < NQ; ++cw) {
            int c  = (cw < NQ - 1) ? cw : NQ - 1;
            int t  = (cw < NQ - 1) ? cw + 1 : 0;
            int mc = 1 << (NQ - 1 - c), mt = 1 << (NQ - 1 - t);
            for (int i = 0; i < DIM; ++i) {
                if ((i & mc) && !(i & mt)) {
                    float2 a = M[i][tid];
                    M[i][tid]      = M[i | mt][tid];
                    M[i | mt][tid] = a;
                }
            }
            __syncthreads();
        }
    }

    // Variational layers
    int idx = 0;
    for (int layer = 0; layer < 2; ++layer) {
        for (int w = 0; w < NQ; ++w) {
            float al = params[idx], be = params[idx + 1], ga = params[idx + 2];
            idx += 3;
            float ca, sa, cb, sb, cg, sg;
            sincosf(0.5f * al, &sa, &ca);
            sincosf(0.5f * be, &sb, &cb);
            sincosf(0.5f * ga, &sg, &cg);
            float2 X00 = make_float2(ca, 0.f),  X01 = make_float2(0.f, -sa);
            float2 X10 = make_float2(0.f, -sa), X11 = make_float2(ca, 0.f);
            float2 Y00 = make_float2(cb, 0.f),  Y01 = make_float2(-sb, 0.f);
            float2 Y10 = make_float2(sb, 0.f),  Y11 = make_float2(cb, 0.f);
            float2 A00 = cadd(cmul(Y00, X00), cmul(Y01, X10));
            float2 A01 = cadd(cmul(Y00, X01), cmul(Y01, X11));
            float2 A10 = cadd(cmul(Y10, X00), cmul(Y11, X10));
            float2 A11 = cadd(cmul(Y10, X01), cmul(Y11, X11));
            float2 Z0 = make_float2(cg, -sg), Z1 = make_float2(cg, sg);
            float2 u00 = cmul(Z0, A00), u01 = cmul(Z0, A01);
            float2 u10 = cmul(Z1, A10), u11 = cmul(Z1, A11);
            int m = 1 << (NQ - 1 - w);
            for (int i0 = 0; i0 < DIM; ++i0) {
                if (i0 & m) continue;
                float2 a = M[i0][tid], b = M[i0 | m][tid];
                M[i0][tid]     = cadd(cmul(u00, a), cmul(u01, b));
                M[i0 | m][tid] = cadd(cmul(u10, a), cmul(u11, b));
            }
            __syncthreads();
        }
        for (int c = 0; c < NQ - 1; ++c) {
            int t  = c + 1;
            int mc = 1 << (NQ - 1 - c), mt = 1 << (NQ - 1 - t);
            for (int i = 0; i < DIM; ++i) {
                if ((i & mc) && !(i & mt)) {
                    float2 a = M[i][tid];
                    M[i][tid]      = M[i | mt][tid];
                    M[i | mt][tid] = a;
                }
            }
            __syncthreads();
        }
    }

    for (int j = 0; j < DIM; ++j)
        U_g[dir][tid][j] = M[tid][j];
}

// ---------------------------------------------------------------------------
// Main scan: 64 threads (2 warps), thread = row. (re,im) packed in f32x2.
// 3 barriers/step. h-state lives in registers (shfl broadcast, no shared).
// Wire w <-> row bit (5-w): wire0 cross-warp (mask 32), wires 1..5 in-warp
// (masks 16,8,4,2,1). RY wires 0+1 fused into one 4-point shared exchange;
// wires 2+3 and 4+5 fused shfl levels. WHT in-warp fused (16,8),(4,2),(1);
// cross-warp WHT level replaced by per-warp partials + designated combine.
// ---------------------------------------------------------------------------
__global__ void __launch_bounds__(64, 1)
hydra_kernel(const float* __restrict__ angles,
             const float* __restrict__ fwd_coeff,
             const float* __restrict__ bwd_coeff,
             float* __restrict__ out)
{
    const int cta  = blockIdx.x;
    const int dir  = cta >> 7;
    const int b    = cta & 127;
    const int tid  = threadIdx.x;   // row 0..63
    const int lane = tid & 31;
    const int warp = tid >> 5;

    // U row packed: Ud[j] = (re, im) of U[row][j] as f32x2
    u64 Ud[DIM];
    {
        const u64* Up = (const u64*)U_g[dir][tid];
#pragma unroll
        for (int j = 0; j < DIM; ++j) Ud[j] = Up[j];
    }

    __shared__ float2 xt[TT * NQ];   // (cos x/2, sin x/2) per (t, w)
    __shared__ u64    p0d[DIM];      // psi0 duplicated-packed (v, v)
    __shared__ float2 ex2[DIM];      // (re, im) cross-warp exchange
    __shared__ float2 fin[NQ];       // per-wire (warp0 partial, warp1 partial)

    // one-time: HALF-ANGLE cos/sin table
    for (int idx = tid; idx < TT * NQ; idx += 64) {
        float a = angles[(size_t)b * (TT * NQ) + idx];
        float s, c; __sincosf(0.5f * a, &s, &c);
        xt[idx] = make_float2(c, s);
    }

    float cf    = dir ? bwd_coeff[0] : fwd_coeff[0];
    float coeff = 1.0f / (1.0f + expf(-cf));
    const size_t outbase = (size_t)b * TT * NQ;

    const unsigned FULL = 0xFFFFFFFFu;
    // designated lanes: 0,1,2,4,8,16 -> wires 0,5,4,3,2,1
    const bool desig = ((lane & (lane - 1)) == 0);
    const int  wire  = (lane == 0) ? 0 : (5 - (31 - __clz(lane)));

    // h state in registers: (cos h_w/2, sin h_w/2), h = 0 initially
    float c0h = 1.f, s0h = 0.f, c1h = 1.f, s1h = 0.f, c2h = 1.f, s2h = 0.f;
    float c3h = 1.f, s3h = 0.f, c4h = 1.f, s4h = 0.f, c5h = 1.f, s5h = 0.f;

    __syncthreads();   // xt ready

    for (int step = 0; step < TT; ++step) {
        const int t = dir ? (TT - 1 - step) : step;

        // psi0[tid] = prod_w (bit_{5-w} ? sin : cos), duplicated-packed
        float va = ((tid >> 5) & 1 ? s0h : c0h)
                 * ((tid >> 4) & 1 ? s1h : c1h)
                 * ((tid >> 3) & 1 ? s2h : c2h);
        float vb = ((tid >> 2) & 1 ? s3h : c3h)
                 * ((tid >> 1) & 1 ? s4h : c4h)
                 * ((tid     ) & 1 ? s5h : c5h);
        float v0 = va * vb;
        p0d[tid] = pack2(v0, v0);
        __syncthreads();                               // B1: p0 ready

        // RY(x) coefficients for this step (broadcast LDS, hidden under matvec)
        float2 X0 = xt[t * NQ + 0], X1 = xt[t * NQ + 1], X2 = xt[t * NQ + 2];
        float2 X3 = xt[t * NQ + 3], X4 = xt[t * NQ + 4], X5 = xt[t * NQ + 5];

        // matvec: (re,im) += U[row][j] * psi0[j], packed f32x2
        u64 a0 = 0ull, a1 = 0ull, a2 = 0ull, a3 = 0ull;
        const ulonglong2* pq = (const ulonglong2*)p0d;
#pragma unroll
        for (int jj = 0; jj < DIM / 4; ++jj) {
            ulonglong2 q0 = pq[2 * jj], q1 = pq[2 * jj + 1];
            ffma2(a0, Ud[4 * jj + 0], q0.x);
            ffma2(a1, Ud[4 * jj + 1], q0.y);
            ffma2(a2, Ud[4 * jj + 2], q1.x);
            ffma2(a3, Ud[4 * jj + 3], q1.y);
        }
        float re, im;
        unpack2(addf2(addf2(a0, a1), addf2(a2, a3)), re, im);

        // RY wires 0,1 (masks 32,16): fused 4-point via shared
        ex2[tid] = make_float2(re, im);
        __syncthreads();                               // B2
        {
            float sg0 = (tid & 32) ? X0.y : -X0.y;
            float sg1 = (tid & 16) ? X1.y : -X1.y;
            float2 e32 = ex2[tid ^ 32], e16 = ex2[tid ^ 16], e48 = ex2[tid ^ 48];
            float k00 = X0.x * X1.x, k10 = sg0 * X1.x, k01 = X0.x * sg1, k11 = sg0 * sg1;
            re = k00 * re + k10 * e32.x + k01 * e16.x + k11 * e48.x;
            im = k00 * im + k10 * e32.y + k01 * e16.y + k11 * e48.y;
        }
        // RY wires 2,3 (masks 8,4): fused shfl level
        {
            float sg2 = (tid & 8) ? X2.y : -X2.y;
            float sg3 = (tid & 4) ? X3.y : -X3.y;
            float r8  = __shfl_xor_sync(FULL, re, 8),  i8  = __shfl_xor_sync(FULL, im, 8);
            float r4  = __shfl_xor_sync(FULL, re, 4),  i4  = __shfl_xor_sync(FULL, im, 4);
            float r12 = __shfl_xor_sync(FULL, re, 12), i12 = __shfl_xor_sync(FULL, im, 12);
            float k00 = X2.x * X3.x, k10 = sg2 * X3.x, k01 = X2.x * sg3, k11 = sg2 * sg3;
            re = k00 * re + k10 * r8 + k01 * r4 + k11 * r12;
            im = k00 * im + k10 * i8 + k01 * i4 + k11 * i12;
        }
        // RY wires 4,5 (masks 2,1): fused shfl level
        {
            float sg4 = (tid & 2) ? X4.y : -X4.y;
            float sg5 = (tid & 1) ? X5.y : -X5.y;
            float r2 = __shfl_xor_sync(FULL, re, 2), i2 = __shfl_xor_sync(FULL, im, 2);
            float r1 = __shfl_xor_sync(FULL, re, 1), i1 = __shfl_xor_sync(FULL, im, 1);
            float r3 = __shfl_xor_sync(FULL, re, 3), i3 = __shfl_xor_sync(FULL, im, 3);
            float k00 = X4.x * X5.x, k10 = sg4 * X5.x, k01 = X4.x * sg5, k11 = sg4 * sg5;
            re = k00 * re + k10 * r2 + k01 * r1 + k11 * r3;
            im = k00 * im + k10 * i2 + k01 * i1 + k11 * i3;
        }

        // probabilities + in-warp WHT (fused (16,8),(4,2),(1))
        float p = fmaf(re, re, im * im);
        {
            float g16 = (tid & 16) ? -1.f : 1.f;
            float g8  = (tid &  8) ? -1.f : 1.f;
            float p16 = __shfl_xor_sync(FULL, p, 16);
            float p8  = __shfl_xor_sync(FULL, p, 8);
            float p24 = __shfl_xor_sync(FULL, p, 24);
            p = g16 * g8 * p + g8 * p16 + g16 * p8 + p24;
        }
        {
            float g4 = (tid & 4) ? -1.f : 1.f;
            float g2 = (tid & 2) ? -1.f : 1.f;
            float p4 = __shfl_xor_sync(FULL, p, 4);
            float p2 = __shfl_xor_sync(FULL, p, 2);
            float p6 = __shfl_xor_sync(FULL, p, 6);
            p = g4 * g2 * p + g2 * p4 + g4 * p2 + p6;
        }
        {
            float g1 = (tid & 1) ? -1.f : 1.f;
            float p1 = __shfl_xor_sync(FULL, p, 1);
            p = g1 * p + p1;
        }
        // lane (1<<(5-w)) holds warp-partial <Z_w> (w>=1); lane 0 holds warp total
        if (desig) ((float*)fin)[wire * 2 + warp] = p;
        __syncthreads();                               // B3

        // BOTH warps' designated lanes combine redundantly (kills hcs barrier)
        float ch = 1.f, sh = 0.f;
        if (desig) {
            float2 f = fin[wire];
            float z = (wire == 0) ? (f.x - f.y) : (f.x + f.y);
            if (warp == 0)
                atomicAdd(&out[outbase + (size_t)t * NQ + wire], coeff * z);
            __sincosf(0.5f * z, &sh, &ch);
        }
        // broadcast (c,s) per wire via in-warp 64-bit shfl — no barrier
        u64 cspk = pack2(ch, sh);
        u64 q;
        q = __shfl_sync(FULL, cspk, 0);  unpack2(q, c0h, s0h);
        q = __shfl_sync(FULL, cspk, 16); unpack2(q, c1h, s1h);
        q = __shfl_sync(FULL, cspk, 8);  unpack2(q, c2h, s2h);
        q = __shfl_sync(FULL, cspk, 4);  unpack2(q, c3h, s3h);
        q = __shfl_sync(FULL, cspk, 2);  unpack2(q, c4h, s4h);
        q = __shfl_sync(FULL, cspk, 1);  unpack2(q, c5h, s5h);
    }
}

__global__ void zero_kernel(float* __restrict__ out, int n)
{
    int i = blockIdx.x * blockDim.x + threadIdx.x;
    if (i < n) out[i] = 0.f;
}

extern "C" void kernel_launch(void* const* d_in, const int* in_sizes, int n_in,
                              void* d_out, int out_size)
{
    const float* angles = (const float*)d_in[0];
    const float* poly   = (const float*)d_in[1];
    const float* fwdp   = (const float*)d_in[2];
    const float* bwdp   = (const float*)d_in[3];
    const float* fwdc   = (const float*)d_in[4];
    const float* bwdc   = (const float*)d_in[5];
    float* out = (float*)d_out;

    zero_kernel<<<(out_size + 255) / 256, 256>>>(out, out_size);
    setup_kernel<<<2, 64>>>(poly, fwdp, bwdp);
    hydra_kernel<<<2 * BB, 64>>>(angles, fwdc, bwdc, out);
}

// round 17
// speedup vs baseline: 2.0997x; 1.1871x over previous
#include <cuda_runtime.h>

#define NQ   6
#define DIM  64
#define TT   512
#define BB   128

typedef unsigned long long u64;

// Fixed per-direction unitaries: U[dir][row][col], built by setup_kernel.
__device__ float2 U_g[2][DIM][DIM];

__device__ __forceinline__ float2 cmul(float2 a, float2 b) {
    return make_float2(a.x * b.x - a.y * b.y, a.x * b.y + a.y * b.x);
}
__device__ __forceinline__ float2 cadd(float2 a, float2 b) {
    return make_float2(a.x + b.x, a.y + b.y);
}

// packed f32x2 helpers (sm_100+)
__device__ __forceinline__ void ffma2(u64& acc, u64 a, u64 b) {
    asm("fma.rn.f32x2 %0, %1, %2, %0;" : "+l"(acc) : "l"(a), "l"(b));
}
__device__ __forceinline__ u64 addf2(u64 a, u64 b) {
    u64 r; asm("add.rn.f32x2 %0, %1, %2;" : "=l"(r) : "l"(a), "l"(b)); return r;
}
__device__ __forceinline__ u64 pack2(float lo, float hi) {
    u64 r;
    asm("mov.b64 %0, {%1, %2};" : "=l"(r)
        : "r"(__float_as_uint(lo)), "r"(__float_as_uint(hi)));
    return r;
}
__device__ __forceinline__ void unpack2(u64 v, float& lo, float& hi) {
    unsigned a, b;
    asm("mov.b64 {%0, %1}, %2;" : "=r"(a), "=r"(b) : "l"(v));
    lo = __uint_as_float(a); hi = __uint_as_float(b);
}
__device__ __forceinline__ u64 dup2(float v) { return pack2(v, v); }

// ---------------------------------------------------------------------------
// Setup: build U = V(params) * Q(poly) as a 64x64 complex matrix per direction.
// ---------------------------------------------------------------------------
__global__ void setup_kernel(const float* __restrict__ poly,
                             const float* __restrict__ fwd_params,
                             const float* __restrict__ bwd_params)
{
    __shared__ float2 M[DIM][DIM];
    const int dir = blockIdx.x;
    const float* params = dir ? bwd_params : fwd_params;
    const int tid = threadIdx.x;  // 0..63

    for (int j = 0; j < DIM; ++j)
        M[tid][j] = make_float2(tid == j ? 1.f : 0.f, 0.f);
    __syncthreads();

    // QSVT block: 4 x (diagonal phase, then CNOT ring)
    for (int d = 0; d <= 3; ++d) {
        float theta = poly[d] * 3.14159265358979323846f;
        float sign  = (float)NQ - 2.0f * (float)__popc(tid);
        float ang   = -0.5f * theta * sign;
        float2 ph;
        sincosf(ang, &ph.y, &ph.x);
        for (int j = 0; j < DIM; ++j)
            M[tid][j] = cmul(ph, M[tid][j]);
        __syncthreads();
        for (int cw = 0; cw < NQ; ++cw) {
            int c  = (cw < NQ - 1) ? cw : NQ - 1;
            int t  = (cw < NQ - 1) ? cw + 1 : 0;
            int mc = 1 << (NQ - 1 - c), mt = 1 << (NQ - 1 - t);
            for (int i = 0; i < DIM; ++i) {
                if ((i & mc) && !(i & mt)) {
                    float2 a = M[i][tid];
                    M[i][tid]      = M[i | mt][tid];
                    M[i | mt][tid] = a;
                }
            }
            __syncthreads();
        }
    }

    // Variational layers
    int idx = 0;
    for (int layer = 0; layer < 2; ++layer) {
        for (int w = 0; w < NQ; ++w) {
            float al = params[idx], be = params[idx + 1], ga = params[idx + 2];
            idx += 3;
            float ca, sa, cb, sb, cg, sg;
            sincosf(0.5f * al, &sa, &ca);
            sincosf(0.5f * be, &sb, &cb);
            sincosf(0.5f * ga, &sg, &cg);
            float2 X00 = make_float2(ca, 0.f),  X01 = make_float2(0.f, -sa);
            float2 X10 = make_float2(0.f, -sa), X11 = make_float2(ca, 0.f);
            float2 Y00 = make_float2(cb, 0.f),  Y01 = make_float2(-sb, 0.f);
            float2 Y10 = make_float2(sb, 0.f),  Y11 = make_float2(cb, 0.f);
            float2 A00 = cadd(cmul(Y00, X00), cmul(Y01, X10));
            float2 A01 = cadd(cmul(Y00, X01), cmul(Y01, X11));
            float2 A10 = cadd(cmul(Y10, X00), cmul(Y11, X10));
            float2 A11 = cadd(cmul(Y10, X01), cmul(Y11, X11));
            float2 Z0 = make_float2(cg, -sg), Z1 = make_float2(cg, sg);
            float2 u00 = cmul(Z0, A00), u01 = cmul(Z0, A01);
            float2 u10 = cmul(Z1, A10), u11 = cmul(Z1, A11);
            int m = 1 << (NQ - 1 - w);
            for (int i0 = 0; i0 < DIM; ++i0) {
                if (i0 & m) continue;
                float2 a = M[i0][tid], b = M[i0 | m][tid];
                M[i0][tid]     = cadd(cmul(u00, a), cmul(u01, b));
                M[i0 | m][tid] = cadd(cmul(u10, a), cmul(u11, b));
            }
            __syncthreads();
        }
        for (int c = 0; c < NQ - 1; ++c) {
            int t  = c + 1;
            int mc = 1 << (NQ - 1 - c), mt = 1 << (NQ - 1 - t);
            for (int i = 0; i < DIM; ++i) {
                if ((i & mc) && !(i & mt)) {
                    float2 a = M[i][tid];
                    M[i][tid]      = M[i | mt][tid];
                    M[i | mt][tid] = a;
                }
            }
            __syncthreads();
        }
    }

    for (int j = 0; j < DIM; ++j)
        U_g[dir][tid][j] = M[tid][j];
}

// ---------------------------------------------------------------------------
// Main scan: 64 threads (2 warps), thread = row. (re,im) packed in f32x2.
// 2 barriers/step. psi0 never touches shared: it is a tensor product
// psi0[8*hi+lo] = va[hi]*vb[lo] with va/vb built in registers from the
// shfl-broadcast h state, and the matvec is the two-stage contraction
//   v_r = sum_hi va[hi] * (sum_lo U[r][8hi+lo] * vb[lo]).
// Wire w <-> row bit (5-w): wire0 cross-warp (mask 32), wires 1..5 in-warp.
// RY wires 0+1 fused 4-point via shared (B2); wires 2+3, 4+5 fused shfl.
// WHT in-warp fused; cross-warp level via per-warp partials + combine (B3).
// ---------------------------------------------------------------------------
__global__ void __launch_bounds__(64, 1)
hydra_kernel(const float* __restrict__ angles,
             const float* __restrict__ fwd_coeff,
             const float* __restrict__ bwd_coeff,
             float* __restrict__ out)
{
    const int cta  = blockIdx.x;
    const int dir  = cta >> 7;
    const int b    = cta & 127;
    const int tid  = threadIdx.x;   // row 0..63
    const int lane = tid & 31;
    const int warp = tid >> 5;

    // U row packed: Ud[j] = (re, im) of U[row][j] as f32x2
    u64 Ud[DIM];
    {
        const u64* Up = (const u64*)U_g[dir][tid];
#pragma unroll
        for (int j = 0; j < DIM; ++j) Ud[j] = Up[j];
    }

    __shared__ float2 xt[TT * NQ];   // (cos x/2, sin x/2) per (t, w)
    __shared__ float2 ex2[DIM];      // (re, im) cross-warp exchange
    __shared__ float2 fin[NQ];       // per-wire (warp0 partial, warp1 partial)

    // one-time: HALF-ANGLE cos/sin table
    for (int idx = tid; idx < TT * NQ; idx += 64) {
        float a = angles[(size_t)b * (TT * NQ) + idx];
        float s, c; __sincosf(0.5f * a, &s, &c);
        xt[idx] = make_float2(c, s);
    }

    float cf    = dir ? bwd_coeff[0] : fwd_coeff[0];
    float coeff = 1.0f / (1.0f + expf(-cf));
    const size_t outbase = (size_t)b * TT * NQ;

    const unsigned FULL = 0xFFFFFFFFu;
    // designated lanes: 0,1,2,4,8,16 -> wires 0,5,4,3,2,1
    const bool desig = ((lane & (lane - 1)) == 0);
    const int  wire  = (lane == 0) ? 0 : (5 - (31 - __clz(lane)));

    // h state in registers: (cos h_w/2, sin h_w/2), h = 0 initially
    float c0h = 1.f, s0h = 0.f, c1h = 1.f, s1h = 0.f, c2h = 1.f, s2h = 0.f;
    float c3h = 1.f, s3h = 0.f, c4h = 1.f, s4h = 0.f, c5h = 1.f, s5h = 0.f;

    __syncthreads();   // xt ready

    for (int step = 0; step < TT; ++step) {
        const int t = dir ? (TT - 1 - step) : step;

        // psi0 tensor-product halves in registers (all threads identical):
        // va over wires 0,1,2 (row bits 5,4,3), vb over wires 3,4,5 (bits 2,1,0)
        u64 vap[8], vbp[8];
        {
            float p00 = c0h * c1h, p01 = c0h * s1h, p10 = s0h * c1h, p11 = s0h * s1h;
            vap[0] = dup2(p00 * c2h); vap[1] = dup2(p00 * s2h);
            vap[2] = dup2(p01 * c2h); vap[3] = dup2(p01 * s2h);
            vap[4] = dup2(p10 * c2h); vap[5] = dup2(p10 * s2h);
            vap[6] = dup2(p11 * c2h); vap[7] = dup2(p11 * s2h);
            float q00 = c3h * c4h, q01 = c3h * s4h, q10 = s3h * c4h, q11 = s3h * s4h;
            vbp[0] = dup2(q00 * c5h); vbp[1] = dup2(q00 * s5h);
            vbp[2] = dup2(q01 * c5h); vbp[3] = dup2(q01 * s5h);
            vbp[4] = dup2(q10 * c5h); vbp[5] = dup2(q10 * s5h);
            vbp[6] = dup2(q11 * c5h); vbp[7] = dup2(q11 * s5h);
        }

        // RY(x) coefficients for this step (broadcast LDS, hidden under matvec)
        float2 X0 = xt[t * NQ + 0], X1 = xt[t * NQ + 1], X2 = xt[t * NQ + 2];
        float2 X3 = xt[t * NQ + 3], X4 = xt[t * NQ + 4], X5 = xt[t * NQ + 5];

        // matvec: v_r = sum_hi vap[hi] * (sum_lo Ud[8hi+lo] * vbp[lo])
        u64 acc[8];
#pragma unroll
        for (int hi = 0; hi < 8; ++hi) {
            u64 a = 0ull;
#pragma unroll
            for (int lo = 0; lo < 8; ++lo)
                ffma2(a, Ud[8 * hi + lo], vbp[lo]);
            acc[hi] = a;
        }
        u64 r0p = 0ull, r1p = 0ull;
#pragma unroll
        for (int hi = 0; hi < 8; hi += 2) {
            ffma2(r0p, vap[hi],     acc[hi]);
            ffma2(r1p, vap[hi + 1], acc[hi + 1]);
        }
        float re, im;
        unpack2(addf2(r0p, r1p), re, im);

        // RY wires 0,1 (masks 32,16): fused 4-point via shared
        ex2[tid] = make_float2(re, im);
        __syncthreads();                               // B2
        {
            float sg0 = (tid & 32) ? X0.y : -X0.y;
            float sg1 = (tid & 16) ? X1.y : -X1.y;
            float2 e32 = ex2[tid ^ 32], e16 = ex2[tid ^ 16], e48 = ex2[tid ^ 48];
            float k00 = X0.x * X1.x, k10 = sg0 * X1.x, k01 = X0.x * sg1, k11 = sg0 * sg1;
            re = k00 * re + k10 * e32.x + k01 * e16.x + k11 * e48.x;
            im = k00 * im + k10 * e32.y + k01 * e16.y + k11 * e48.y;
        }
        // RY wires 2,3 (masks 8,4): fused shfl level
        {
            float sg2 = (tid & 8) ? X2.y : -X2.y;
            float sg3 = (tid & 4) ? X3.y : -X3.y;
            float r8  = __shfl_xor_sync(FULL, re, 8),  i8  = __shfl_xor_sync(FULL, im, 8);
            float r4  = __shfl_xor_sync(FULL, re, 4),  i4  = __shfl_xor_sync(FULL, im, 4);
            float r12 = __shfl_xor_sync(FULL, re, 12), i12 = __shfl_xor_sync(FULL, im, 12);
            float k00 = X2.x * X3.x, k10 = sg2 * X3.x, k01 = X2.x * sg3, k11 = sg2 * sg3;
            re = k00 * re + k10 * r8 + k01 * r4 + k11 * r12;
            im = k00 * im + k10 * i8 + k01 * i4 + k11 * i12;
        }
        // RY wires 4,5 (masks 2,1): fused shfl level
        {
            float sg4 = (tid & 2) ? X4.y : -X4.y;
            float sg5 = (tid & 1) ? X5.y : -X5.y;
            float r2 = __shfl_xor_sync(FULL, re, 2), i2 = __shfl_xor_sync(FULL, im, 2);
            float r1 = __shfl_xor_sync(FULL, re, 1), i1 = __shfl_xor_sync(FULL, im, 1);
            float r3 = __shfl_xor_sync(FULL, re, 3), i3 = __shfl_xor_sync(FULL, im, 3);
            float k00 = X4.x * X5.x, k10 = sg4 * X5.x, k01 = X4.x * sg5, k11 = sg4 * sg5;
            re = k00 * re + k10 * r2 + k01 * r1 + k11 * r3;
            im = k00 * im + k10 * i2 + k01 * i1 + k11 * i3;
        }

        // probabilities + in-warp WHT (fused (16,8),(4,2),(1))
        float p = fmaf(re, re, im * im);
        {
            float g16 = (tid & 16) ? -1.f : 1.f;
            float g8  = (tid &  8) ? -1.f : 1.f;
            float p16 = __shfl_xor_sync(FULL, p, 16);
            float p8  = __shfl_xor_sync(FULL, p, 8);
            float p24 = __shfl_xor_sync(FULL, p, 24);
            p = g16 * g8 * p + g8 * p16 + g16 * p8 + p24;
        }
        {
            float g4 = (tid & 4) ? -1.f : 1.f;
            float g2 = (tid & 2) ? -1.f : 1.f;
            float p4 = __shfl_xor_sync(FULL, p, 4);
            float p2 = __shfl_xor_sync(FULL, p, 2);
            float p6 = __shfl_xor_sync(FULL, p, 6);
            p = g4 * g2 * p + g2 * p4 + g4 * p2 + p6;
        }
        {
            float g1 = (tid & 1) ? -1.f : 1.f;
            float p1 = __shfl_xor_sync(FULL, p, 1);
            p = g1 * p + p1;
        }
        // lane (1<<(5-w)) holds warp-partial <Z_w> (w>=1); lane 0 holds warp total
        if (desig) ((float*)fin)[wire * 2 + warp] = p;
        __syncthreads();                               // B3

        // BOTH warps' designated lanes combine redundantly (no extra barrier)
        float ch = 1.f, sh = 0.f;
        if (desig) {
            float2 f = fin[wire];
            float z = (wire == 0) ? (f.x - f.y) : (f.x + f.y);
            if (warp == 0)
                atomicAdd(&out[outbase + (size_t)t * NQ + wire], coeff * z);
            __sincosf(0.5f * z, &sh, &ch);
        }
        // broadcast (c,s) per wire via in-warp 64-bit shfl — no barrier
        u64 cspk = pack2(ch, sh);
        u64 q;
        q = __shfl_sync(FULL, cspk, 0);  unpack2(q, c0h, s0h);
        q = __shfl_sync(FULL, cspk, 16); unpack2(q, c1h, s1h);
        q = __shfl_sync(FULL, cspk, 8);  unpack2(q, c2h, s2h);
        q = __shfl_sync(FULL, cspk, 4);  unpack2(q, c3h, s3h);
        q = __shfl_sync(FULL, cspk, 2);  unpack2(q, c4h, s4h);
        q = __shfl_sync(FULL, cspk, 1);  unpack2(q, c5h, s5h);
    }
}

__global__ void zero_kernel(float* __restrict__ out, int n)
{
    int i = blockIdx.x * blockDim.x + threadIdx.x;
    if (i < n) out[i] = 0.f;
}

extern "C" void kernel_launch(void* const* d_in, const int* in_sizes, int n_in,
                              void* d_out, int out_size)
{
    const float* angles = (const float*)d_in[0];
    const float* poly   = (const float*)d_in[1];
    const float* fwdp   = (const float*)d_in[2];
    const float* bwdp   = (const float*)d_in[3];
    const float* fwdc   = (const float*)d_in[4];
    const float* bwdc   = (const float*)d_in[5];
    float* out = (float*)d_out;

    zero_kernel<<<(out_size + 255) / 256, 256>>>(out, out_size);
    setup_kernel<<<2, 64>>>(poly, fwdp, bwdp);
    hydra_kernel<<<2 * BB, 64>>>(angles, fwdc, bwdc, out);
}